// round 4
// baseline (speedup 1.0000x reference)
// GraphConvolution_49177375539507 — fused tf32 mma.sync kernel for GB300 (sm_103a)
//
// out[b] = sum_e adj[b,e] @ (node[b] @ W_e + b_e)  +  node[b] @ W_add + b_add
//
// One CTA per b (grid 512), 256 threads (8 warps), each warp owns a 32-row band.
// node (tf32) and hidden_e (tf32) live in XOR-swizzled smem; adj streams through
// a cp.async double buffer (row stride 36 floats -> conflict-free A-frag LDS).
// adj is used as raw fp32 bits in the tf32 mma (hardware truncation, ~1e-4 bias);
// node/W/hidden are rounded with cvt.rna.tf32 once at smem store.

#include <cuda_runtime.h>
#include <cstdint>

#define N_SZ 256
#define F_SZ 64
#define E_SZ 4
#define NTHREADS 256
#define ADJ_STRIDE 36           // floats per row in the adj smem chunk (pad for banks)
#define ADJ_BUF_FLOATS (256 * ADJ_STRIDE)   // 9216 floats per buffer

// smem layout (floats)
#define SH_NODE 0               // 256*64 = 16384
#define SH_HID  16384           // 256*64 = 16384
#define SH_W    32768           // 64*64  = 4096
#define SH_BIAS 36864           // 64
#define SH_ADJ  36928           // 2 * 9216 = 18432
#define SMEM_FLOATS 55360
#define SMEM_BYTES (SMEM_FLOATS * 4)        // 221440 B

__device__ __forceinline__ int swz(int r, int c) { return c ^ ((r & 3) << 3); }

__device__ __forceinline__ uint32_t f2tf(float f) {
    uint32_t r;
    asm("cvt.rna.tf32.f32 %0, %1;" : "=r"(r) : "f"(f));
    return r;
}

__device__ __forceinline__ void mma_tf32(float (&d)[4], const uint32_t (&a)[4],
                                         const uint32_t (&b)[2]) {
    asm volatile(
        "mma.sync.aligned.m16n8k8.row.col.f32.tf32.tf32.f32 "
        "{%0,%1,%2,%3}, {%4,%5,%6,%7}, {%8,%9}, {%0,%1,%2,%3};\n"
        : "+f"(d[0]), "+f"(d[1]), "+f"(d[2]), "+f"(d[3])
        : "r"(a[0]), "r"(a[1]), "r"(a[2]), "r"(a[3]), "r"(b[0]), "r"(b[1]));
}

__device__ __forceinline__ void cp_async16(void* smem_ptr, const void* gmem_ptr) {
    unsigned sa = (unsigned)__cvta_generic_to_shared(smem_ptr);
    asm volatile("cp.async.cg.shared.global [%0], [%1], 16;\n" :: "r"(sa), "l"(gmem_ptr));
}
__device__ __forceinline__ void cp_commit() { asm volatile("cp.async.commit_group;\n"); }
template <int N> __device__ __forceinline__ void cp_wait() {
    asm volatile("cp.async.wait_group %0;\n" :: "n"(N));
}

// hidden/residual stage: acc[j][nt] += node(warp rows, tf32 in smem) @ sh_w
__device__ __forceinline__ void gemm_nodeW(const float* __restrict__ sh_node,
                                           const float* __restrict__ sh_w,
                                           int mrow, int qr, int qc,
                                           float (&acc)[2][8][4]) {
    const int swa = (qr & 3) << 3;
#pragma unroll
    for (int s = 0; s < 8; ++s) {
        uint32_t bf[8][2];
        const int kr0 = 8 * s + qc;
#pragma unroll
        for (int nt = 0; nt < 8; ++nt) {
            const int cc = (8 * nt + qr) ^ (qc << 3);
            bf[nt][0] = *(const uint32_t*)&sh_w[kr0 * 64 + cc];
            bf[nt][1] = *(const uint32_t*)&sh_w[(kr0 + 4) * 64 + cc];
        }
#pragma unroll
        for (int j = 0; j < 2; ++j) {
            const int r0 = mrow + 16 * j + qr;
            uint32_t af[4];
            af[0] = *(const uint32_t*)&sh_node[r0 * 64 + ((8 * s + qc) ^ swa)];
            af[1] = *(const uint32_t*)&sh_node[(r0 + 8) * 64 + ((8 * s + qc) ^ swa)];
            af[2] = *(const uint32_t*)&sh_node[r0 * 64 + ((8 * s + qc + 4) ^ swa)];
            af[3] = *(const uint32_t*)&sh_node[(r0 + 8) * 64 + ((8 * s + qc + 4) ^ swa)];
#pragma unroll
            for (int nt = 0; nt < 8; ++nt) mma_tf32(acc[j][nt], af, bf[nt]);
        }
    }
}

__device__ __forceinline__ void load_W_bias(float* __restrict__ sh_w,
                                            float* __restrict__ sh_bias,
                                            const float* __restrict__ W,
                                            const float* __restrict__ bv, int tid) {
    const float4* src = (const float4*)W;
#pragma unroll
    for (int i = 0; i < 4; ++i) {
        const int idx = tid + i * NTHREADS;       // 1024 float4 total
        const int r = idx >> 4;
        const int c = (idx & 15) << 2;
        float4 v = src[idx];
        uint32_t* dst = (uint32_t*)&sh_w[r * 64 + swz(r, c)];
        dst[0] = f2tf(v.x); dst[1] = f2tf(v.y); dst[2] = f2tf(v.z); dst[3] = f2tf(v.w);
    }
    if (tid < 64) sh_bias[tid] = bv[tid];
}

__device__ __forceinline__ void init_bias(const float* __restrict__ sh_bias, int qc,
                                          float (&acc)[2][8][4]) {
#pragma unroll
    for (int nt = 0; nt < 8; ++nt) {
        const float v0 = sh_bias[8 * nt + 2 * qc];
        const float v1 = sh_bias[8 * nt + 2 * qc + 1];
#pragma unroll
        for (int j = 0; j < 2; ++j) {
            acc[j][nt][0] = v0; acc[j][nt][1] = v1;
            acc[j][nt][2] = v0; acc[j][nt][3] = v1;
        }
    }
}

__device__ __forceinline__ void issue_adj_chunk(float* __restrict__ buf,
                                                const float* __restrict__ adj_be,
                                                int kc, int tid) {
    const int row = tid >> 3;                  // 0..31
    const int cf = (tid & 7) << 2;             // float offset within 32-wide chunk
    const float* src = adj_be + row * 256 + kc * 32 + cf;
    float* dst = buf + row * ADJ_STRIDE + cf;
#pragma unroll
    for (int ii = 0; ii < 8; ++ii)
        cp_async16(dst + ii * 32 * ADJ_STRIDE, src + ii * 32 * 256);
}

__global__ void __launch_bounds__(NTHREADS, 1)
graphconv_tf32_kernel(const float* __restrict__ node,
                      const float* __restrict__ adj,
                      const float* __restrict__ W_edge,
                      const float* __restrict__ b_edge,
                      const float* __restrict__ W_add,
                      const float* __restrict__ b_add,
                      float* __restrict__ out) {
    extern __shared__ float smem[];
    float* sh_node = smem + SH_NODE;
    float* sh_hid  = smem + SH_HID;
    float* sh_w    = smem + SH_W;
    float* sh_bias = smem + SH_BIAS;
    float* sh_adj  = smem + SH_ADJ;

    const int tid  = threadIdx.x;
    const int w    = tid >> 5;
    const int lane = tid & 31;
    const int qr   = lane >> 2;
    const int qc   = lane & 3;
    const int mrow = w << 5;
    const int b    = blockIdx.x;

    // ---- stage node[b] into smem (tf32, swizzled), coalesced float4 ----
    {
        const float4* src = (const float4*)(node + (size_t)b * N_SZ * F_SZ);
#pragma unroll
        for (int i = 0; i < 16; ++i) {
            const int idx = tid + i * NTHREADS;   // 4096 float4 total
            const int r = idx >> 4;
            const int c = (idx & 15) << 2;
            float4 v = src[idx];
            uint32_t* dst = (uint32_t*)&sh_node[r * 64 + swz(r, c)];
            dst[0] = f2tf(v.x); dst[1] = f2tf(v.y); dst[2] = f2tf(v.z); dst[3] = f2tf(v.w);
        }
    }

    // ---- residual: out_acc = node @ W_add + b_add ----
    load_W_bias(sh_w, sh_bias, W_add, b_add, tid);
    __syncthreads();   // node + W_add + bias visible

    float oacc[2][8][4];
    init_bias(sh_bias, qc, oacc);
    gemm_nodeW(sh_node, sh_w, mrow, qr, qc, oacc);

    // ---- edge-type loop ----
    for (int e = 0; e < E_SZ; ++e) {
        __syncthreads();   // all readers of sh_w / sh_hid (prev iter) done
        load_W_bias(sh_w, sh_bias, W_edge + e * 4096, b_edge + e * 64, tid);
        __syncthreads();   // W_e + bias visible

        // stage 1: hidden_e = node @ W_e + b_e  -> sh_hid (tf32, swizzled)
        float hacc[2][8][4];
        init_bias(sh_bias, qc, hacc);
        gemm_nodeW(sh_node, sh_w, mrow, qr, qc, hacc);
#pragma unroll
        for (int j = 0; j < 2; ++j) {
#pragma unroll
            for (int nt = 0; nt < 8; ++nt) {
                const int r0 = mrow + 16 * j + qr;
                const int c0 = 8 * nt + 2 * qc;
                *(float2*)&sh_hid[r0 * 64 + swz(r0, c0)] =
                    make_float2(__uint_as_float(f2tf(hacc[j][nt][0])),
                                __uint_as_float(f2tf(hacc[j][nt][1])));
                *(float2*)&sh_hid[(r0 + 8) * 64 + swz(r0 + 8, c0)] =
                    make_float2(__uint_as_float(f2tf(hacc[j][nt][2])),
                                __uint_as_float(f2tf(hacc[j][nt][3])));
            }
        }
        __syncthreads();   // hidden visible to all warps

        // stage 2: out_acc += adj_e @ hidden_e, streaming adj in 256x32 chunks
        const float* adj_be = adj + (((size_t)(b * E_SZ + e)) << 16);
        issue_adj_chunk(sh_adj, adj_be, 0, tid);
        cp_commit();

        for (int kc = 0; kc < 8; ++kc) {
            if (kc < 7) {
                issue_adj_chunk(sh_adj + ((kc + 1) & 1) * ADJ_BUF_FLOATS, adj_be, kc + 1, tid);
                cp_commit();
                cp_wait<1>();
            } else {
                cp_wait<0>();
            }
            __syncthreads();   // chunk kc visible to all threads

            const float* abuf = sh_adj + (kc & 1) * ADJ_BUF_FLOATS;
#pragma unroll
            for (int s = 0; s < 4; ++s) {
                const int kr0 = 32 * kc + 8 * s + qc;   // hidden row (global k)
                uint32_t bf[8][2];
#pragma unroll
                for (int nt = 0; nt < 8; ++nt) {
                    const int cc = (8 * nt + qr) ^ (qc << 3);
                    bf[nt][0] = *(const uint32_t*)&sh_hid[kr0 * 64 + cc];
                    bf[nt][1] = *(const uint32_t*)&sh_hid[(kr0 + 4) * 64 + cc];
                }
#pragma unroll
                for (int j = 0; j < 2; ++j) {
                    const int r0 = mrow + 16 * j + qr;
                    const int cl = 8 * s + qc;
                    uint32_t af[4];
                    af[0] = *(const uint32_t*)&abuf[r0 * ADJ_STRIDE + cl];
                    af[1] = *(const uint32_t*)&abuf[(r0 + 8) * ADJ_STRIDE + cl];
                    af[2] = *(const uint32_t*)&abuf[r0 * ADJ_STRIDE + cl + 4];
                    af[3] = *(const uint32_t*)&abuf[(r0 + 8) * ADJ_STRIDE + cl + 4];
#pragma unroll
                    for (int nt = 0; nt < 8; ++nt) mma_tf32(oacc[j][nt], af, bf[nt]);
                }
            }
            __syncthreads();   // buffer (kc&1) free for reuse before next issue
        }
    }

    // ---- epilogue: write out[b] ----
    float* ob = out + (size_t)b * N_SZ * F_SZ;
#pragma unroll
    for (int j = 0; j < 2; ++j) {
#pragma unroll
        for (int nt = 0; nt < 8; ++nt) {
            const int r0 = mrow + 16 * j + qr;
            const int c0 = 8 * nt + 2 * qc;
            *(float2*)&ob[r0 * 64 + c0]       = make_float2(oacc[j][nt][0], oacc[j][nt][1]);
            *(float2*)&ob[(r0 + 8) * 64 + c0] = make_float2(oacc[j][nt][2], oacc[j][nt][3]);
        }
    }
}

extern "C" void kernel_launch(void* const* d_in, const int* in_sizes, int n_in,
                              void* d_out, int out_size) {
    const float* node   = (const float*)d_in[0];
    const float* adj    = (const float*)d_in[1];
    const float* W_edge = (const float*)d_in[2];
    const float* b_edge = (const float*)d_in[3];
    const float* W_add  = (const float*)d_in[4];
    const float* b_add  = (const float*)d_in[5];
    float* out = (float*)d_out;

    cudaFuncSetAttribute(graphconv_tf32_kernel,
                         cudaFuncAttributeMaxDynamicSharedMemorySize, SMEM_BYTES);
    graphconv_tf32_kernel<<<512, NTHREADS, SMEM_BYTES>>>(node, adj, W_edge, b_edge,
                                                         W_add, b_add, out);
}

// round 6
// speedup vs baseline: 1.1221x; 1.1221x over previous
// GraphConvolution_49177375539507 — fused tf32 mma.sync kernel for GB300 (sm_103a)
// R4: per-warp adj cp.async pipelines (no block barriers in the hot loop),
//     adj prefetch overlapped with the hidden GEMM.
//
// out[b] = sum_e adj[b,e] @ (node[b] @ W_e + b_e)  +  node[b] @ W_add + b_add
//
// One CTA per b (grid 512), 256 threads (8 warps), each warp owns a 32-row band.
// node (tf32) and hidden_e (tf32) live in XOR-swizzled smem (shared across warps);
// adj streams through PER-WARP double buffers (32x32 chunks, row stride 36 floats
// -> conflict-free A-frag LDS), synchronized with cp.async.wait_group + __syncwarp
// only. adj is fed as raw fp32 bits to the tf32 mma (HW truncation ~1e-4 bias);
// node/W/hidden are rounded with cvt.rna.tf32 once at smem store.

#include <cuda_runtime.h>
#include <cstdint>

#define N_SZ 256
#define F_SZ 64
#define E_SZ 4
#define NTHREADS 256
#define ADJ_STRIDE 36                    // floats per row in a warp's adj chunk
#define WBUF_FLOATS (32 * ADJ_STRIDE)    // 1152 floats per buffer per warp

// smem layout (floats)
#define SH_NODE 0               // 256*64 = 16384
#define SH_HID  16384           // 256*64 = 16384
#define SH_W    32768           // 64*64  = 4096
#define SH_BIAS 36864           // 64
#define SH_ADJ  36928           // 8 warps * 2 bufs * 1152 = 18432
#define SMEM_FLOATS 55360
#define SMEM_BYTES (SMEM_FLOATS * 4)     // 221440 B

__device__ __forceinline__ int swz(int r, int c) { return c ^ ((r & 3) << 3); }

__device__ __forceinline__ uint32_t f2tf(float f) {
    uint32_t r;
    asm("cvt.rna.tf32.f32 %0, %1;" : "=r"(r) : "f"(f));
    return r;
}

__device__ __forceinline__ void mma_tf32(float (&d)[4], const uint32_t (&a)[4],
                                         const uint32_t (&b)[2]) {
    asm volatile(
        "mma.sync.aligned.m16n8k8.row.col.f32.tf32.tf32.f32 "
        "{%0,%1,%2,%3}, {%4,%5,%6,%7}, {%8,%9}, {%0,%1,%2,%3};\n"
        : "+f"(d[0]), "+f"(d[1]), "+f"(d[2]), "+f"(d[3])
        : "r"(a[0]), "r"(a[1]), "r"(a[2]), "r"(a[3]), "r"(b[0]), "r"(b[1]));
}

__device__ __forceinline__ void cp_async16(void* smem_ptr, const void* gmem_ptr) {
    unsigned sa = (unsigned)__cvta_generic_to_shared(smem_ptr);
    asm volatile("cp.async.cg.shared.global [%0], [%1], 16;\n" :: "r"(sa), "l"(gmem_ptr));
}
__device__ __forceinline__ void cp_commit() { asm volatile("cp.async.commit_group;\n"); }
template <int N> __device__ __forceinline__ void cp_wait() {
    asm volatile("cp.async.wait_group %0;\n" :: "n"(N));
}

// Per-warp adj chunk load: this warp's 32 rows x 32 cols (chunk kc) of adj[b,e].
// Lane -> (row = lane>>3, 16B piece = (lane&7)*16B): 128B-coalesced per row.
__device__ __forceinline__ void issue_adj_warp(float* __restrict__ wbuf,
                                               const float* __restrict__ adj_w,
                                               int kc, int lane) {
    const int row = lane >> 3;                 // 0..3
    const int cf  = (lane & 7) << 2;           // float offset within 32-col chunk
    const float* src = adj_w + row * 256 + kc * 32 + cf;
    float* dst = wbuf + row * ADJ_STRIDE + cf;
#pragma unroll
    for (int ii = 0; ii < 8; ++ii)
        cp_async16(dst + ii * 4 * ADJ_STRIDE, src + ii * 4 * 256);
}

// hidden/residual stage: acc[j][nt] += node(warp rows, tf32 in smem) @ sh_w
__device__ __forceinline__ void gemm_nodeW(const float* __restrict__ sh_node,
                                           const float* __restrict__ sh_w,
                                           int mrow, int qr, int qc,
                                           float (&acc)[2][8][4]) {
    const int swa = (qr & 3) << 3;
#pragma unroll
    for (int s = 0; s < 8; ++s) {
        uint32_t bf[8][2];
        const int kr0 = 8 * s + qc;
#pragma unroll
        for (int nt = 0; nt < 8; ++nt) {
            const int cc = (8 * nt + qr) ^ (qc << 3);
            bf[nt][0] = *(const uint32_t*)&sh_w[kr0 * 64 + cc];
            bf[nt][1] = *(const uint32_t*)&sh_w[(kr0 + 4) * 64 + cc];
        }
#pragma unroll
        for (int j = 0; j < 2; ++j) {
            const int r0 = mrow + 16 * j + qr;
            uint32_t af[4];
            af[0] = *(const uint32_t*)&sh_node[r0 * 64 + ((8 * s + qc) ^ swa)];
            af[1] = *(const uint32_t*)&sh_node[(r0 + 8) * 64 + ((8 * s + qc) ^ swa)];
            af[2] = *(const uint32_t*)&sh_node[r0 * 64 + ((8 * s + qc + 4) ^ swa)];
            af[3] = *(const uint32_t*)&sh_node[(r0 + 8) * 64 + ((8 * s + qc + 4) ^ swa)];
#pragma unroll
            for (int nt = 0; nt < 8; ++nt) mma_tf32(acc[j][nt], af, bf[nt]);
        }
    }
}

__device__ __forceinline__ void load_W_bias(float* __restrict__ sh_w,
                                            float* __restrict__ sh_bias,
                                            const float* __restrict__ W,
                                            const float* __restrict__ bv, int tid) {
    const float4* src = (const float4*)W;
#pragma unroll
    for (int i = 0; i < 4; ++i) {
        const int idx = tid + i * NTHREADS;       // 1024 float4 total
        const int r = idx >> 4;
        const int c = (idx & 15) << 2;
        float4 v = src[idx];
        uint32_t* dst = (uint32_t*)&sh_w[r * 64 + swz(r, c)];
        dst[0] = f2tf(v.x); dst[1] = f2tf(v.y); dst[2] = f2tf(v.z); dst[3] = f2tf(v.w);
    }
    if (tid < 64) sh_bias[tid] = bv[tid];
}

__device__ __forceinline__ void init_bias(const float* __restrict__ sh_bias, int qc,
                                          float (&acc)[2][8][4]) {
#pragma unroll
    for (int nt = 0; nt < 8; ++nt) {
        const float v0 = sh_bias[8 * nt + 2 * qc];
        const float v1 = sh_bias[8 * nt + 2 * qc + 1];
#pragma unroll
        for (int j = 0; j < 2; ++j) {
            acc[j][nt][0] = v0; acc[j][nt][1] = v1;
            acc[j][nt][2] = v0; acc[j][nt][3] = v1;
        }
    }
}

__global__ void __launch_bounds__(NTHREADS, 1)
graphconv_tf32_kernel(const float* __restrict__ node,
                      const float* __restrict__ adj,
                      const float* __restrict__ W_edge,
                      const float* __restrict__ b_edge,
                      const float* __restrict__ W_add,
                      const float* __restrict__ b_add,
                      float* __restrict__ out) {
    extern __shared__ float smem[];
    float* sh_node = smem + SH_NODE;
    float* sh_hid  = smem + SH_HID;
    float* sh_w    = smem + SH_W;
    float* sh_bias = smem + SH_BIAS;

    const int tid  = threadIdx.x;
    const int w    = tid >> 5;
    const int lane = tid & 31;
    const int qr   = lane >> 2;
    const int qc   = lane & 3;
    const int mrow = w << 5;
    const int b    = blockIdx.x;

    float* wbuf = smem + SH_ADJ + w * 2 * WBUF_FLOATS;   // this warp's double buffer

    // ---- kick off edge-0 adj chunks 0,1 for this warp's row band immediately ----
    const float* adj_b = adj + (((size_t)b * E_SZ) << 16);
    {
        const float* adj_w0 = adj_b + mrow * 256;
        issue_adj_warp(wbuf,               adj_w0, 0, lane); cp_commit();
        issue_adj_warp(wbuf + WBUF_FLOATS, adj_w0, 1, lane); cp_commit();
    }

    // ---- stage node[b] into smem (tf32, swizzled), coalesced float4 ----
    {
        const float4* src = (const float4*)(node + (size_t)b * N_SZ * F_SZ);
#pragma unroll
        for (int i = 0; i < 16; ++i) {
            const int idx = tid + i * NTHREADS;   // 4096 float4 total
            const int r = idx >> 4;
            const int c = (idx & 15) << 2;
            float4 v = src[idx];
            uint32_t* dst = (uint32_t*)&sh_node[r * 64 + swz(r, c)];
            dst[0] = f2tf(v.x); dst[1] = f2tf(v.y); dst[2] = f2tf(v.z); dst[3] = f2tf(v.w);
        }
    }

    // ---- residual: out_acc = node @ W_add + b_add (overlaps edge-0 adj loads) ----
    load_W_bias(sh_w, sh_bias, W_add, b_add, tid);
    __syncthreads();   // node + W_add + bias visible

    float oacc[2][8][4];
    init_bias(sh_bias, qc, oacc);
    gemm_nodeW(sh_node, sh_w, mrow, qr, qc, oacc);

    // ---- edge-type loop ----
    for (int e = 0; e < E_SZ; ++e) {
        const float* adj_w = adj_b + ((size_t)e << 16) + mrow * 256;

        if (e > 0) {   // e==0 chunks already in flight; buffers free (drained last edge)
            issue_adj_warp(wbuf,               adj_w, 0, lane); cp_commit();
            issue_adj_warp(wbuf + WBUF_FLOATS, adj_w, 1, lane); cp_commit();
        }

        // W_e + bias_e load overlaps the in-flight adj chunks
        load_W_bias(sh_w, sh_bias, W_edge + e * 4096, b_edge + e * 64, tid);
        __syncthreads();   // W_e/bias visible; also: every warp done with prev
                           // edge's sh_hid reads and prev gemm's sh_w reads

        // stage 1: hidden_e = node @ W_e + b_e  -> sh_hid (tf32, swizzled)
        float hacc[2][8][4];
        init_bias(sh_bias, qc, hacc);
        gemm_nodeW(sh_node, sh_w, mrow, qr, qc, hacc);
#pragma unroll
        for (int j = 0; j < 2; ++j) {
#pragma unroll
            for (int nt = 0; nt < 8; ++nt) {
                const int r0 = mrow + 16 * j + qr;
                const int c0 = 8 * nt + 2 * qc;
                *(float2*)&sh_hid[r0 * 64 + swz(r0, c0)] =
                    make_float2(__uint_as_float(f2tf(hacc[j][nt][0])),
                                __uint_as_float(f2tf(hacc[j][nt][1])));
                *(float2*)&sh_hid[(r0 + 8) * 64 + swz(r0 + 8, c0)] =
                    make_float2(__uint_as_float(f2tf(hacc[j][nt][2])),
                                __uint_as_float(f2tf(hacc[j][nt][3])));
            }
        }
        __syncthreads();   // hidden visible to all warps

        // stage 2: out_acc += adj_e @ hidden_e — per-warp pipeline, NO block syncs
        for (int kc = 0; kc < 8; ++kc) {
            if (kc < 7) cp_wait<1>(); else cp_wait<0>();
            __syncwarp();   // chunk kc landed for all lanes of this warp

            const float* abuf = wbuf + (kc & 1) * WBUF_FLOATS;
#pragma unroll
            for (int s = 0; s < 4; ++s) {
                const int kr0 = 32 * kc + 8 * s + qc;   // hidden row (global k)
                uint32_t bf[8][2];
#pragma unroll
                for (int nt = 0; nt < 8; ++nt) {
                    const int cc = (8 * nt + qr) ^ (qc << 3);
                    bf[nt][0] = *(const uint32_t*)&sh_hid[kr0 * 64 + cc];
                    bf[nt][1] = *(const uint32_t*)&sh_hid[(kr0 + 4) * 64 + cc];
                }
#pragma unroll
                for (int j = 0; j < 2; ++j) {
                    const int lr = 16 * j + qr;          // local row in warp buffer
                    const int cl = 8 * s + qc;
                    uint32_t af[4];
                    af[0] = *(const uint32_t*)&abuf[lr * ADJ_STRIDE + cl];
                    af[1] = *(const uint32_t*)&abuf[(lr + 8) * ADJ_STRIDE + cl];
                    af[2] = *(const uint32_t*)&abuf[lr * ADJ_STRIDE + cl + 4];
                    af[3] = *(const uint32_t*)&abuf[(lr + 8) * ADJ_STRIDE + cl + 4];
#pragma unroll
                    for (int nt = 0; nt < 8; ++nt) mma_tf32(oacc[j][nt], af, bf[nt]);
                }
            }

            if (kc < 6) {
                __syncwarp();   // all lanes done reading buf (kc&1) before refill
                issue_adj_warp(wbuf + (kc & 1) * WBUF_FLOATS, adj_w, kc + 2, lane);
                cp_commit();
            }
        }
        __syncwarp();   // last chunk's reads done before next edge refills buffers
    }

    // ---- epilogue: write out[b] ----
    float* ob = out + (size_t)b * N_SZ * F_SZ;
#pragma unroll
    for (int j = 0; j < 2; ++j) {
#pragma unroll
        for (int nt = 0; nt < 8; ++nt) {
            const int r0 = mrow + 16 * j + qr;
            const int c0 = 8 * nt + 2 * qc;
            *(float2*)&ob[r0 * 64 + c0]       = make_float2(oacc[j][nt][0], oacc[j][nt][1]);
            *(float2*)&ob[(r0 + 8) * 64 + c0] = make_float2(oacc[j][nt][2], oacc[j][nt][3]);
        }
    }
}

extern "C" void kernel_launch(void* const* d_in, const int* in_sizes, int n_in,
                              void* d_out, int out_size) {
    const float* node   = (const float*)d_in[0];
    const float* adj    = (const float*)d_in[1];
    const float* W_edge = (const float*)d_in[2];
    const float* b_edge = (const float*)d_in[3];
    const float* W_add  = (const float*)d_in[4];
    const float* b_add  = (const float*)d_in[5];
    float* out = (float*)d_out;

    cudaFuncSetAttribute(graphconv_tf32_kernel,
                         cudaFuncAttributeMaxDynamicSharedMemorySize, SMEM_BYTES);
    graphconv_tf32_kernel<<<512, NTHREADS, SMEM_BYTES>>>(node, adj, W_edge, b_edge,
                                                         W_add, b_add, out);
}

// round 7
// speedup vs baseline: 1.1408x; 1.0167x over previous
// GraphConvolution_49177375539507 — fused tf32 mma.sync kernel for GB300 (sm_103a)
// R6: 16 warps x 16 rows, node A-fragments in registers (sh_node deleted),
//     4-stage per-warp adj cp.async pipeline, pair-interleaved hidden layout
//     (LDS.64 B-fragments).
//
// out[b] = sum_e adj[b,e] @ (node[b] @ W_e + b_e)  +  node[b] @ W_add + b_add
//
// One CTA per b (grid 512), 512 threads (16 warps), each warp owns 16 output rows.
// hidden_e (tf32) is block-shared in a pair-interleaved smem layout; adj streams
// through PER-WARP 4-stage buffers (16x32 chunks, row stride 36 -> conflict-free
// A-frag LDS), synchronized with cp.async.wait_group + __syncwarp only.
// adj is fed as raw fp32 bits to the tf32 mma (HW truncation ~1e-4 bias);
// node/W/hidden are rounded with cvt.rna.tf32.

#include <cuda_runtime.h>
#include <cstdint>

#define N_SZ 256
#define F_SZ 64
#define E_SZ 4
#define NTHREADS 512
#define NWARPS 16
#define MR 16                            // output rows per warp
#define ADJ_STRIDE 36                    // floats per row in a warp's adj chunk
#define WBUF_FLOATS (MR * ADJ_STRIDE)    // 576 floats per stage per warp
#define NSTAGE 4
#define NODE_STRIDE 68                   // node staging stride (startup only)

// smem layout (floats)
#define SH_HID  0                        // 256*64 = 16384 (pair-interleaved)
#define SH_W    16384                    // 64*64  = 4096
#define SH_BIAS 20480                    // 64
#define SH_ADJ  20544                    // 16 warps * 4 stages * 576 = 36864
#define SMEM_FLOATS 57408
#define SMEM_BYTES (SMEM_FLOATS * 4)     // 229632 B

__device__ __forceinline__ int swz(int r, int c) { return c ^ ((r & 3) << 3); }

// pair-interleaved hidden address: (k,n) and (k+4,n) are adjacent words
__device__ __forceinline__ int paddr(int k, int n) {
    return ((k >> 3) << 9) + (n << 3) + ((k & 3) << 1) + ((k >> 2) & 1);
}

__device__ __forceinline__ uint32_t f2tf(float f) {
    uint32_t r;
    asm("cvt.rna.tf32.f32 %0, %1;" : "=r"(r) : "f"(f));
    return r;
}

__device__ __forceinline__ void mma_tf32(float (&d)[4], const uint32_t (&a)[4],
                                         const uint32_t (&b)[2]) {
    asm volatile(
        "mma.sync.aligned.m16n8k8.row.col.f32.tf32.tf32.f32 "
        "{%0,%1,%2,%3}, {%4,%5,%6,%7}, {%8,%9}, {%0,%1,%2,%3};\n"
        : "+f"(d[0]), "+f"(d[1]), "+f"(d[2]), "+f"(d[3])
        : "r"(a[0]), "r"(a[1]), "r"(a[2]), "r"(a[3]), "r"(b[0]), "r"(b[1]));
}

__device__ __forceinline__ void cp_async16(void* smem_ptr, const void* gmem_ptr) {
    unsigned sa = (unsigned)__cvta_generic_to_shared(smem_ptr);
    asm volatile("cp.async.cg.shared.global [%0], [%1], 16;\n" :: "r"(sa), "l"(gmem_ptr));
}
__device__ __forceinline__ void cp_commit() { asm volatile("cp.async.commit_group;\n"); }
template <int N> __device__ __forceinline__ void cp_wait() {
    asm volatile("cp.async.wait_group %0;\n" :: "n"(N));
}

// Per-warp adj chunk load: this warp's 16 rows x 32 cols (chunk kc) of adj[b,e].
__device__ __forceinline__ void issue_adj_warp(float* __restrict__ wbuf,
                                               const float* __restrict__ adj_w,
                                               int kc, int lane) {
    const int row = lane >> 3;                 // 0..3
    const int cf  = (lane & 7) << 2;           // float offset within 32-col chunk
    const float* src = adj_w + row * 256 + kc * 32 + cf;
    float* dst = wbuf + row * ADJ_STRIDE + cf;
#pragma unroll
    for (int ii = 0; ii < 4; ++ii)
        cp_async16(dst + ii * 4 * ADJ_STRIDE, src + ii * 4 * 256);
}

// hidden/residual stage: acc[nt] += nodefrag(regs) @ sh_w (old XOR-swizzled layout)
__device__ __forceinline__ void gemm_nodeW(const uint32_t (&naf)[8][4],
                                           const float* __restrict__ sh_w,
                                           int qr, int qc,
                                           float (&acc)[8][4]) {
#pragma unroll
    for (int s = 0; s < 8; ++s) {
        uint32_t bf[8][2];
        const int kr0 = 8 * s + qc;
#pragma unroll
        for (int nt = 0; nt < 8; ++nt) {
            const int cc = (8 * nt + qr) ^ (qc << 3);
            bf[nt][0] = *(const uint32_t*)&sh_w[kr0 * 64 + cc];
            bf[nt][1] = *(const uint32_t*)&sh_w[(kr0 + 4) * 64 + cc];
        }
#pragma unroll
        for (int nt = 0; nt < 8; ++nt) mma_tf32(acc[nt], naf[s], bf[nt]);
    }
}

__device__ __forceinline__ void load_W_bias(float* __restrict__ sh_w,
                                            float* __restrict__ sh_bias,
                                            const float* __restrict__ W,
                                            const float* __restrict__ bv, int tid) {
    const float4* src = (const float4*)W;
#pragma unroll
    for (int i = 0; i < 2; ++i) {
        const int idx = tid + i * NTHREADS;       // 1024 float4 total
        const int r = idx >> 4;
        const int c = (idx & 15) << 2;
        float4 v = src[idx];
        uint32_t* dst = (uint32_t*)&sh_w[r * 64 + swz(r, c)];
        dst[0] = f2tf(v.x); dst[1] = f2tf(v.y); dst[2] = f2tf(v.z); dst[3] = f2tf(v.w);
    }
    if (tid < 64) sh_bias[tid] = bv[tid];
}

__device__ __forceinline__ void init_bias(const float* __restrict__ sh_bias, int qc,
                                          float (&acc)[8][4]) {
#pragma unroll
    for (int nt = 0; nt < 8; ++nt) {
        const float v0 = sh_bias[8 * nt + 2 * qc];
        const float v1 = sh_bias[8 * nt + 2 * qc + 1];
        acc[nt][0] = v0; acc[nt][1] = v1;
        acc[nt][2] = v0; acc[nt][3] = v1;
    }
}

__global__ void __launch_bounds__(NTHREADS, 1)
graphconv_tf32_kernel(const float* __restrict__ node,
                      const float* __restrict__ adj,
                      const float* __restrict__ W_edge,
                      const float* __restrict__ b_edge,
                      const float* __restrict__ W_add,
                      const float* __restrict__ b_add,
                      float* __restrict__ out) {
    extern __shared__ float smem[];
    float* sh_hid  = smem + SH_HID;
    float* sh_w    = smem + SH_W;
    float* sh_bias = smem + SH_BIAS;

    const int tid  = threadIdx.x;
    const int w    = tid >> 5;
    const int lane = tid & 31;
    const int qr   = lane >> 2;
    const int qc   = lane & 3;
    const int mrow = w * MR;
    const int b    = blockIdx.x;

    float* wbuf = smem + SH_ADJ + w * NSTAGE * WBUF_FLOATS;  // this warp's 4 stages

    // ---- stage this warp's 16x64 node band via its adj buffers, build A-frags ----
    uint32_t naf[8][4];
    {
        const float* gnode = node + (size_t)b * N_SZ * F_SZ + mrow * F_SZ;
#pragma unroll
        for (int i = 0; i < 8; ++i) {
            const int p = lane + 32 * i;       // 256 x 16B pieces
            const int r = p >> 4;
            const int cf = (p & 15) << 2;
            cp_async16(wbuf + r * NODE_STRIDE + cf, gnode + r * 64 + cf);
        }
        cp_commit();
        cp_wait<0>();
        __syncwarp();
#pragma unroll
        for (int s = 0; s < 8; ++s) {
            naf[s][0] = f2tf(wbuf[qr * NODE_STRIDE + 8 * s + qc]);
            naf[s][1] = f2tf(wbuf[(qr + 8) * NODE_STRIDE + 8 * s + qc]);
            naf[s][2] = f2tf(wbuf[qr * NODE_STRIDE + 8 * s + qc + 4]);
            naf[s][3] = f2tf(wbuf[(qr + 8) * NODE_STRIDE + 8 * s + qc + 4]);
        }
        __syncwarp();   // frag extraction done before adj loads overwrite buffers
    }

    const float* adj_b = adj + (((size_t)b * E_SZ) << 16);

    // ---- kick off edge-0 adj chunks 0..2 immediately ----
    {
        const float* adj_w0 = adj_b + mrow * 256;
        issue_adj_warp(wbuf,                   adj_w0, 0, lane); cp_commit();
        issue_adj_warp(wbuf + 1 * WBUF_FLOATS, adj_w0, 1, lane); cp_commit();
        issue_adj_warp(wbuf + 2 * WBUF_FLOATS, adj_w0, 2, lane); cp_commit();
    }

    // ---- residual: out_acc = node @ W_add + b_add (overlaps edge-0 adj loads) ----
    load_W_bias(sh_w, sh_bias, W_add, b_add, tid);
    __syncthreads();   // W_add + bias visible

    float oacc[8][4];
    init_bias(sh_bias, qc, oacc);
    gemm_nodeW(naf, sh_w, qr, qc, oacc);

    // ---- edge-type loop ----
    for (int e = 0; e < E_SZ; ++e) {
        const float* adj_w = adj_b + ((size_t)e << 16) + mrow * 256;

        if (e > 0) {   // e==0 chunks already in flight; buffers drained last edge
            issue_adj_warp(wbuf,                   adj_w, 0, lane); cp_commit();
            issue_adj_warp(wbuf + 1 * WBUF_FLOATS, adj_w, 1, lane); cp_commit();
            issue_adj_warp(wbuf + 2 * WBUF_FLOATS, adj_w, 2, lane); cp_commit();
        }

        __syncthreads();   // all warps done with prev sh_w reads + prev sh_hid reads
        load_W_bias(sh_w, sh_bias, W_edge + e * 4096, b_edge + e * 64, tid);
        __syncthreads();   // W_e + bias visible

        // stage 1: hidden_e = node @ W_e + b_e  -> sh_hid (tf32, pair-interleaved)
        {
            float hacc[8][4];
            init_bias(sh_bias, qc, hacc);
            gemm_nodeW(naf, sh_w, qr, qc, hacc);
#pragma unroll
            for (int nt = 0; nt < 8; ++nt) {
                const int a0 = ((mrow >> 3) << 9) + ((8 * nt + 2 * qc) << 3)
                             + ((qr & 3) << 1) + (qr >> 2);
                sh_hid[a0]       = __uint_as_float(f2tf(hacc[nt][0]));   // (k=mrow+qr,   n)
                sh_hid[a0 + 8]   = __uint_as_float(f2tf(hacc[nt][1]));   // (k,           n+1)
                sh_hid[a0 + 512] = __uint_as_float(f2tf(hacc[nt][2]));   // (k+8,         n)
                sh_hid[a0 + 520] = __uint_as_float(f2tf(hacc[nt][3]));   // (k+8,         n+1)
            }
        }
        __syncthreads();   // hidden visible to all warps

        // stage 2: out_acc += adj_e @ hidden_e — per-warp 4-stage pipeline
#pragma unroll
        for (int kc = 0; kc < 8; ++kc) {
            __syncwarp();   // all lanes done with chunk kc-1 before its buffer refills
            if (kc < 5) {
                issue_adj_warp(wbuf + ((kc + 3) & 3) * WBUF_FLOATS, adj_w, kc + 3, lane);
                cp_commit();
            }
            if (kc < 5)      cp_wait<3>();
            else if (kc == 5) cp_wait<2>();
            else if (kc == 6) cp_wait<1>();
            else              cp_wait<0>();
            __syncwarp();   // chunk kc visible to all lanes of this warp

            const float* abuf = wbuf + (kc & 3) * WBUF_FLOATS;
#pragma unroll
            for (int s = 0; s < 4; ++s) {
                const float* gbase = sh_hid + (((4 * kc + s)) << 9);
                uint32_t bf[8][2];
#pragma unroll
                for (int nt = 0; nt < 8; ++nt) {
                    // {hid[k0+qc][n], hid[k0+qc+4][n]} as one LDS.64
                    uint2 p = *(const uint2*)&gbase[((8 * nt + qr) << 3) + (qc << 1)];
                    bf[nt][0] = p.x; bf[nt][1] = p.y;
                }
                const int cl = 8 * s + qc;
                uint32_t af[4];
                af[0] = *(const uint32_t*)&abuf[qr * ADJ_STRIDE + cl];
                af[1] = *(const uint32_t*)&abuf[(qr + 8) * ADJ_STRIDE + cl];
                af[2] = *(const uint32_t*)&abuf[qr * ADJ_STRIDE + cl + 4];
                af[3] = *(const uint32_t*)&abuf[(qr + 8) * ADJ_STRIDE + cl + 4];
#pragma unroll
                for (int nt = 0; nt < 8; ++nt) mma_tf32(oacc[nt], af, bf[nt]);
            }
        }
        __syncwarp();   // last chunk's reads done before next edge refills buffers
    }

    // ---- epilogue: write out[b] ----
    float* ob = out + (size_t)b * N_SZ * F_SZ;
#pragma unroll
    for (int nt = 0; nt < 8; ++nt) {
        const int r0 = mrow + qr;
        const int c0 = 8 * nt + 2 * qc;
        *(float2*)&ob[r0 * 64 + c0]       = make_float2(oacc[nt][0], oacc[nt][1]);
        *(float2*)&ob[(r0 + 8) * 64 + c0] = make_float2(oacc[nt][2], oacc[nt][3]);
    }
}

extern "C" void kernel_launch(void* const* d_in, const int* in_sizes, int n_in,
                              void* d_out, int out_size) {
    const float* node   = (const float*)d_in[0];
    const float* adj    = (const float*)d_in[1];
    const float* W_edge = (const float*)d_in[2];
    const float* b_edge = (const float*)d_in[3];
    const float* W_add  = (const float*)d_in[4];
    const float* b_add  = (const float*)d_in[5];
    float* out = (float*)d_out;

    cudaFuncSetAttribute(graphconv_tf32_kernel,
                         cudaFuncAttributeMaxDynamicSharedMemorySize, SMEM_BYTES);
    graphconv_tf32_kernel<<<512, NTHREADS, SMEM_BYTES>>>(node, adj, W_edge, b_edge,
                                                         W_add, b_add, out);
}

// round 8
// speedup vs baseline: 1.1425x; 1.0015x over previous
// GraphConvolution_49177375539507 — fused tf32 mma.sync kernel for GB300 (sm_103a)
// R6: 16 warps x 16 rows, node A-fragments in registers (sh_node deleted),
//     4-stage per-warp adj cp.async pipeline, pair-interleaved hidden layout
//     (LDS.64 B-fragments).
//
// out[b] = sum_e adj[b,e] @ (node[b] @ W_e + b_e)  +  node[b] @ W_add + b_add
//
// One CTA per b (grid 512), 512 threads (16 warps), each warp owns 16 output rows.
// hidden_e (tf32) is block-shared in a pair-interleaved smem layout; adj streams
// through PER-WARP 4-stage buffers (16x32 chunks, row stride 36 -> conflict-free
// A-frag LDS), synchronized with cp.async.wait_group + __syncwarp only.
// adj is fed as raw fp32 bits to the tf32 mma (HW truncation ~1e-4 bias);
// node/W/hidden are rounded with cvt.rna.tf32.

#include <cuda_runtime.h>
#include <cstdint>

#define N_SZ 256
#define F_SZ 64
#define E_SZ 4
#define NTHREADS 512
#define NWARPS 16
#define MR 16                            // output rows per warp
#define ADJ_STRIDE 36                    // floats per row in a warp's adj chunk
#define WBUF_FLOATS (MR * ADJ_STRIDE)    // 576 floats per stage per warp
#define NSTAGE 4
#define NODE_STRIDE 68                   // node staging stride (startup only)

// smem layout (floats)
#define SH_HID  0                        // 256*64 = 16384 (pair-interleaved)
#define SH_W    16384                    // 64*64  = 4096
#define SH_BIAS 20480                    // 64
#define SH_ADJ  20544                    // 16 warps * 4 stages * 576 = 36864
#define SMEM_FLOATS 57408
#define SMEM_BYTES (SMEM_FLOATS * 4)     // 229632 B

__device__ __forceinline__ int swz(int r, int c) { return c ^ ((r & 3) << 3); }

// pair-interleaved hidden address: (k,n) and (k+4,n) are adjacent words
__device__ __forceinline__ int paddr(int k, int n) {
    return ((k >> 3) << 9) + (n << 3) + ((k & 3) << 1) + ((k >> 2) & 1);
}

__device__ __forceinline__ uint32_t f2tf(float f) {
    uint32_t r;
    asm("cvt.rna.tf32.f32 %0, %1;" : "=r"(r) : "f"(f));
    return r;
}

__device__ __forceinline__ void mma_tf32(float (&d)[4], const uint32_t (&a)[4],
                                         const uint32_t (&b)[2]) {
    asm volatile(
        "mma.sync.aligned.m16n8k8.row.col.f32.tf32.tf32.f32 "
        "{%0,%1,%2,%3}, {%4,%5,%6,%7}, {%8,%9}, {%0,%1,%2,%3};\n"
        : "+f"(d[0]), "+f"(d[1]), "+f"(d[2]), "+f"(d[3])
        : "r"(a[0]), "r"(a[1]), "r"(a[2]), "r"(a[3]), "r"(b[0]), "r"(b[1]));
}

__device__ __forceinline__ void cp_async16(void* smem_ptr, const void* gmem_ptr) {
    unsigned sa = (unsigned)__cvta_generic_to_shared(smem_ptr);
    asm volatile("cp.async.cg.shared.global [%0], [%1], 16;\n" :: "r"(sa), "l"(gmem_ptr));
}
__device__ __forceinline__ void cp_commit() { asm volatile("cp.async.commit_group;\n"); }
template <int N> __device__ __forceinline__ void cp_wait() {
    asm volatile("cp.async.wait_group %0;\n" :: "n"(N));
}

// Per-warp adj chunk load: this warp's 16 rows x 32 cols (chunk kc) of adj[b,e].
__device__ __forceinline__ void issue_adj_warp(float* __restrict__ wbuf,
                                               const float* __restrict__ adj_w,
                                               int kc, int lane) {
    const int row = lane >> 3;                 // 0..3
    const int cf  = (lane & 7) << 2;           // float offset within 32-col chunk
    const float* src = adj_w + row * 256 + kc * 32 + cf;
    float* dst = wbuf + row * ADJ_STRIDE + cf;
#pragma unroll
    for (int ii = 0; ii < 4; ++ii)
        cp_async16(dst + ii * 4 * ADJ_STRIDE, src + ii * 4 * 256);
}

// hidden/residual stage: acc[nt] += nodefrag(regs) @ sh_w (old XOR-swizzled layout)
__device__ __forceinline__ void gemm_nodeW(const uint32_t (&naf)[8][4],
                                           const float* __restrict__ sh_w,
                                           int qr, int qc,
                                           float (&acc)[8][4]) {
#pragma unroll
    for (int s = 0; s < 8; ++s) {
        uint32_t bf[8][2];
        const int kr0 = 8 * s + qc;
#pragma unroll
        for (int nt = 0; nt < 8; ++nt) {
            const int cc = (8 * nt + qr) ^ (qc << 3);
            bf[nt][0] = *(const uint32_t*)&sh_w[kr0 * 64 + cc];
            bf[nt][1] = *(const uint32_t*)&sh_w[(kr0 + 4) * 64 + cc];
        }
#pragma unroll
        for (int nt = 0; nt < 8; ++nt) mma_tf32(acc[nt], naf[s], bf[nt]);
    }
}

__device__ __forceinline__ void load_W_bias(float* __restrict__ sh_w,
                                            float* __restrict__ sh_bias,
                                            const float* __restrict__ W,
                                            const float* __restrict__ bv, int tid) {
    const float4* src = (const float4*)W;
#pragma unroll
    for (int i = 0; i < 2; ++i) {
        const int idx = tid + i * NTHREADS;       // 1024 float4 total
        const int r = idx >> 4;
        const int c = (idx & 15) << 2;
        float4 v = src[idx];
        uint32_t* dst = (uint32_t*)&sh_w[r * 64 + swz(r, c)];
        dst[0] = f2tf(v.x); dst[1] = f2tf(v.y); dst[2] = f2tf(v.z); dst[3] = f2tf(v.w);
    }
    if (tid < 64) sh_bias[tid] = bv[tid];
}

__device__ __forceinline__ void init_bias(const float* __restrict__ sh_bias, int qc,
                                          float (&acc)[8][4]) {
#pragma unroll
    for (int nt = 0; nt < 8; ++nt) {
        const float v0 = sh_bias[8 * nt + 2 * qc];
        const float v1 = sh_bias[8 * nt + 2 * qc + 1];
        acc[nt][0] = v0; acc[nt][1] = v1;
        acc[nt][2] = v0; acc[nt][3] = v1;
    }
}

__global__ void __launch_bounds__(NTHREADS, 1)
graphconv_tf32_kernel(const float* __restrict__ node,
                      const float* __restrict__ adj,
                      const float* __restrict__ W_edge,
                      const float* __restrict__ b_edge,
                      const float* __restrict__ W_add,
                      const float* __restrict__ b_add,
                      float* __restrict__ out) {
    extern __shared__ float smem[];
    float* sh_hid  = smem + SH_HID;
    float* sh_w    = smem + SH_W;
    float* sh_bias = smem + SH_BIAS;

    const int tid  = threadIdx.x;
    const int w    = tid >> 5;
    const int lane = tid & 31;
    const int qr   = lane >> 2;
    const int qc   = lane & 3;
    const int mrow = w * MR;
    const int b    = blockIdx.x;

    float* wbuf = smem + SH_ADJ + w * NSTAGE * WBUF_FLOATS;  // this warp's 4 stages

    // ---- stage this warp's 16x64 node band via its adj buffers, build A-frags ----
    uint32_t naf[8][4];
    {
        const float* gnode = node + (size_t)b * N_SZ * F_SZ + mrow * F_SZ;
#pragma unroll
        for (int i = 0; i < 8; ++i) {
            const int p = lane + 32 * i;       // 256 x 16B pieces
            const int r = p >> 4;
            const int cf = (p & 15) << 2;
            cp_async16(wbuf + r * NODE_STRIDE + cf, gnode + r * 64 + cf);
        }
        cp_commit();
        cp_wait<0>();
        __syncwarp();
#pragma unroll
        for (int s = 0; s < 8; ++s) {
            naf[s][0] = f2tf(wbuf[qr * NODE_STRIDE + 8 * s + qc]);
            naf[s][1] = f2tf(wbuf[(qr + 8) * NODE_STRIDE + 8 * s + qc]);
            naf[s][2] = f2tf(wbuf[qr * NODE_STRIDE + 8 * s + qc + 4]);
            naf[s][3] = f2tf(wbuf[(qr + 8) * NODE_STRIDE + 8 * s + qc + 4]);
        }
        __syncwarp();   // frag extraction done before adj loads overwrite buffers
    }

    const float* adj_b = adj + (((size_t)b * E_SZ) << 16);

    // ---- kick off edge-0 adj chunks 0..2 immediately ----
    {
        const float* adj_w0 = adj_b + mrow * 256;
        issue_adj_warp(wbuf,                   adj_w0, 0, lane); cp_commit();
        issue_adj_warp(wbuf + 1 * WBUF_FLOATS, adj_w0, 1, lane); cp_commit();
        issue_adj_warp(wbuf + 2 * WBUF_FLOATS, adj_w0, 2, lane); cp_commit();
    }

    // ---- residual: out_acc = node @ W_add + b_add (overlaps edge-0 adj loads) ----
    load_W_bias(sh_w, sh_bias, W_add, b_add, tid);
    __syncthreads();   // W_add + bias visible

    float oacc[8][4];
    init_bias(sh_bias, qc, oacc);
    gemm_nodeW(naf, sh_w, qr, qc, oacc);

    // ---- edge-type loop ----
    for (int e = 0; e < E_SZ; ++e) {
        const float* adj_w = adj_b + ((size_t)e << 16) + mrow * 256;

        if (e > 0) {   // e==0 chunks already in flight; buffers drained last edge
            issue_adj_warp(wbuf,                   adj_w, 0, lane); cp_commit();
            issue_adj_warp(wbuf + 1 * WBUF_FLOATS, adj_w, 1, lane); cp_commit();
            issue_adj_warp(wbuf + 2 * WBUF_FLOATS, adj_w, 2, lane); cp_commit();
        }

        __syncthreads();   // all warps done with prev sh_w reads + prev sh_hid reads
        load_W_bias(sh_w, sh_bias, W_edge + e * 4096, b_edge + e * 64, tid);
        __syncthreads();   // W_e + bias visible

        // stage 1: hidden_e = node @ W_e + b_e  -> sh_hid (tf32, pair-interleaved)
        {
            float hacc[8][4];
            init_bias(sh_bias, qc, hacc);
            gemm_nodeW(naf, sh_w, qr, qc, hacc);
#pragma unroll
            for (int nt = 0; nt < 8; ++nt) {
                const int a0 = ((mrow >> 3) << 9) + ((8 * nt + 2 * qc) << 3)
                             + ((qr & 3) << 1) + (qr >> 2);
                sh_hid[a0]       = __uint_as_float(f2tf(hacc[nt][0]));   // (k=mrow+qr,   n)
                sh_hid[a0 + 8]   = __uint_as_float(f2tf(hacc[nt][1]));   // (k,           n+1)
                sh_hid[a0 + 512] = __uint_as_float(f2tf(hacc[nt][2]));   // (k+8,         n)
                sh_hid[a0 + 520] = __uint_as_float(f2tf(hacc[nt][3]));   // (k+8,         n+1)
            }
        }
        __syncthreads();   // hidden visible to all warps

        // stage 2: out_acc += adj_e @ hidden_e — per-warp 4-stage pipeline
#pragma unroll
        for (int kc = 0; kc < 8; ++kc) {
            __syncwarp();   // all lanes done with chunk kc-1 before its buffer refills
            if (kc < 5) {
                issue_adj_warp(wbuf + ((kc + 3) & 3) * WBUF_FLOATS, adj_w, kc + 3, lane);
                cp_commit();
            }
            if (kc < 5)      cp_wait<3>();
            else if (kc == 5) cp_wait<2>();
            else if (kc == 6) cp_wait<1>();
            else              cp_wait<0>();
            __syncwarp();   // chunk kc visible to all lanes of this warp

            const float* abuf = wbuf + (kc & 3) * WBUF_FLOATS;
#pragma unroll
            for (int s = 0; s < 4; ++s) {
                const float* gbase = sh_hid + (((4 * kc + s)) << 9);
                uint32_t bf[8][2];
#pragma unroll
                for (int nt = 0; nt < 8; ++nt) {
                    // {hid[k0+qc][n], hid[k0+qc+4][n]} as one LDS.64
                    uint2 p = *(const uint2*)&gbase[((8 * nt + qr) << 3) + (qc << 1)];
                    bf[nt][0] = p.x; bf[nt][1] = p.y;
                }
                const int cl = 8 * s + qc;
                uint32_t af[4];
                af[0] = *(const uint32_t*)&abuf[qr * ADJ_STRIDE + cl];
                af[1] = *(const uint32_t*)&abuf[(qr + 8) * ADJ_STRIDE + cl];
                af[2] = *(const uint32_t*)&abuf[qr * ADJ_STRIDE + cl + 4];
                af[3] = *(const uint32_t*)&abuf[(qr + 8) * ADJ_STRIDE + cl + 4];
#pragma unroll
                for (int nt = 0; nt < 8; ++nt) mma_tf32(oacc[nt], af, bf[nt]);
            }
        }
        __syncwarp();   // last chunk's reads done before next edge refills buffers
    }

    // ---- epilogue: write out[b] ----
    float* ob = out + (size_t)b * N_SZ * F_SZ;
#pragma unroll
    for (int nt = 0; nt < 8; ++nt) {
        const int r0 = mrow + qr;
        const int c0 = 8 * nt + 2 * qc;
        *(float2*)&ob[r0 * 64 + c0]       = make_float2(oacc[nt][0], oacc[nt][1]);
        *(float2*)&ob[(r0 + 8) * 64 + c0] = make_float2(oacc[nt][2], oacc[nt][3]);
    }
}

extern "C" void kernel_launch(void* const* d_in, const int* in_sizes, int n_in,
                              void* d_out, int out_size) {
    const float* node   = (const float*)d_in[0];
    const float* adj    = (const float*)d_in[1];
    const float* W_edge = (const float*)d_in[2];
    const float* b_edge = (const float*)d_in[3];
    const float* W_add  = (const float*)d_in[4];
    const float* b_add  = (const float*)d_in[5];
    float* out = (float*)d_out;

    cudaFuncSetAttribute(graphconv_tf32_kernel,
                         cudaFuncAttributeMaxDynamicSharedMemorySize, SMEM_BYTES);
    graphconv_tf32_kernel<<<512, NTHREADS, SMEM_BYTES>>>(node, adj, W_edge, b_edge,
                                                         W_add, b_add, out);
}

// round 13
// speedup vs baseline: 1.2437x; 1.0887x over previous
// GraphConvolution_49177375539507 — fused tf32 mma.sync kernel for GB300 (sm_103a)
// R10: 8 warps x 32 rows (halves B-frag LDS traffic vs R6), node A-frags in
//      registers, 4-stage per-warp adj cp.async ring with SEAMLESS cross-edge
//      prefetch (slots freed at kc=5..7 refill with next edge's chunks 0..2),
//      pair-interleaved hidden layout (LDS.64 B-frags).
//
// out[b] = sum_e adj[b,e] @ (node[b] @ W_e + b_e)  +  node[b] @ W_add + b_add
//
// One CTA per b (grid 512), 256 threads (8 warps), each warp owns 32 output rows.
// adj is fed as raw fp32 bits to the tf32 mma (HW truncation ~1e-4 bias);
// node/W/hidden are rounded with cvt.rna.tf32.  (tcgen05 unavailable: harness
// builds through compute_103 PTX where tcgen05/.cta_group don't assemble.)

#include <cuda_runtime.h>
#include <cstdint>

#define N_SZ 256
#define F_SZ 64
#define E_SZ 4
#define NTHREADS 256
#define NWARPS 8
#define MR 32                            // output rows per warp
#define ADJ_STRIDE 36                    // floats per row in a warp's adj chunk
#define WBUF_FLOATS (MR * ADJ_STRIDE)    // 1152 floats per stage per warp
#define NSTAGE 4
#define NODE_STRIDE 68                   // node staging stride (startup only)

// smem layout (floats)
#define SH_HID  0                        // 256*64 = 16384 (pair-interleaved)
#define SH_W    16384                    // 64*64  = 4096
#define SH_BIAS 20480                    // 64
#define SH_ADJ  20544                    // 8 warps * 4 stages * 1152 = 36864
#define SMEM_FLOATS 57408
#define SMEM_BYTES (SMEM_FLOATS * 4)     // 229632 B

__device__ __forceinline__ int swz(int r, int c) { return c ^ ((r & 3) << 3); }

__device__ __forceinline__ uint32_t f2tf(float f) {
    uint32_t r;
    asm("cvt.rna.tf32.f32 %0, %1;" : "=r"(r) : "f"(f));
    return r;
}

__device__ __forceinline__ void mma_tf32(float (&d)[4], const uint32_t (&a)[4],
                                         const uint32_t (&b)[2]) {
    asm volatile(
        "mma.sync.aligned.m16n8k8.row.col.f32.tf32.tf32.f32 "
        "{%0,%1,%2,%3}, {%4,%5,%6,%7}, {%8,%9}, {%0,%1,%2,%3};\n"
        : "+f"(d[0]), "+f"(d[1]), "+f"(d[2]), "+f"(d[3])
        : "r"(a[0]), "r"(a[1]), "r"(a[2]), "r"(a[3]), "r"(b[0]), "r"(b[1]));
}

__device__ __forceinline__ void cp_async16(void* smem_ptr, const void* gmem_ptr) {
    unsigned sa = (unsigned)__cvta_generic_to_shared(smem_ptr);
    asm volatile("cp.async.cg.shared.global [%0], [%1], 16;\n" :: "r"(sa), "l"(gmem_ptr));
}
__device__ __forceinline__ void cp_commit() { asm volatile("cp.async.commit_group;\n"); }
template <int N> __device__ __forceinline__ void cp_wait() {
    asm volatile("cp.async.wait_group %0;\n" :: "n"(N));
}

// Per-warp adj chunk load: this warp's 32 rows x 32 cols (chunk kc) of adj[b,e].
// Lane -> (row base = lane>>3, 16B piece = (lane&7)*16B): 128B-coalesced per row.
__device__ __forceinline__ void issue_adj_warp(float* __restrict__ wbuf,
                                               const float* __restrict__ adj_w,
                                               int kc, int lane) {
    const int row = lane >> 3;                 // 0..3
    const int cf  = (lane & 7) << 2;           // float offset within 32-col chunk
    const float* src = adj_w + row * 256 + kc * 32 + cf;
    float* dst = wbuf + row * ADJ_STRIDE + cf;
#pragma unroll
    for (int ii = 0; ii < 8; ++ii)
        cp_async16(dst + ii * 4 * ADJ_STRIDE, src + ii * 4 * 256);
}

// hidden/residual stage: acc[j][nt] += nodefrag(regs) @ sh_w (XOR-swizzled)
__device__ __forceinline__ void gemm_nodeW(const uint32_t (&naf)[2][8][4],
                                           const float* __restrict__ sh_w,
                                           int qr, int qc,
                                           float (&acc)[2][8][4]) {
#pragma unroll
    for (int s = 0; s < 8; ++s) {
        uint32_t bf[8][2];
        const int kr0 = 8 * s + qc;
#pragma unroll
        for (int nt = 0; nt < 8; ++nt) {
            const int cc = (8 * nt + qr) ^ (qc << 3);
            bf[nt][0] = *(const uint32_t*)&sh_w[kr0 * 64 + cc];
            bf[nt][1] = *(const uint32_t*)&sh_w[(kr0 + 4) * 64 + cc];
        }
#pragma unroll
        for (int j = 0; j < 2; ++j)
#pragma unroll
            for (int nt = 0; nt < 8; ++nt) mma_tf32(acc[j][nt], naf[j][s], bf[nt]);
    }
}

__device__ __forceinline__ void load_W_bias(float* __restrict__ sh_w,
                                            float* __restrict__ sh_bias,
                                            const float* __restrict__ W,
                                            const float* __restrict__ bv, int tid) {
    const float4* src = (const float4*)W;
#pragma unroll
    for (int i = 0; i < 4; ++i) {
        const int idx = tid + i * NTHREADS;       // 1024 float4 total
        const int r = idx >> 4;
        const int c = (idx & 15) << 2;
        float4 v = src[idx];
        uint32_t* dst = (uint32_t*)&sh_w[r * 64 + swz(r, c)];
        dst[0] = f2tf(v.x); dst[1] = f2tf(v.y); dst[2] = f2tf(v.z); dst[3] = f2tf(v.w);
    }
    if (tid < 64) sh_bias[tid] = bv[tid];
}

__device__ __forceinline__ void init_bias(const float* __restrict__ sh_bias, int qc,
                                          float (&acc)[2][8][4]) {
#pragma unroll
    for (int nt = 0; nt < 8; ++nt) {
        const float v0 = sh_bias[8 * nt + 2 * qc];
        const float v1 = sh_bias[8 * nt + 2 * qc + 1];
#pragma unroll
        for (int j = 0; j < 2; ++j) {
            acc[j][nt][0] = v0; acc[j][nt][1] = v1;
            acc[j][nt][2] = v0; acc[j][nt][3] = v1;
        }
    }
}

__global__ void __launch_bounds__(NTHREADS, 1)
graphconv_tf32_kernel(const float* __restrict__ node,
                      const float* __restrict__ adj,
                      const float* __restrict__ W_edge,
                      const float* __restrict__ b_edge,
                      const float* __restrict__ W_add,
                      const float* __restrict__ b_add,
                      float* __restrict__ out) {
    extern __shared__ float smem[];
    float* sh_hid  = smem + SH_HID;
    float* sh_w    = smem + SH_W;
    float* sh_bias = smem + SH_BIAS;

    const int tid  = threadIdx.x;
    const int w    = tid >> 5;
    const int lane = tid & 31;
    const int qr   = lane >> 2;
    const int qc   = lane & 3;
    const int mrow = w * MR;
    const int b    = blockIdx.x;

    float* wbuf = smem + SH_ADJ + w * NSTAGE * WBUF_FLOATS;  // this warp's 4 slots

    // ---- stage this warp's 32x64 node band via its ring slots, build A-frags ----
    uint32_t naf[2][8][4];
    {
        const float* gnode = node + (size_t)b * N_SZ * F_SZ + mrow * F_SZ;
#pragma unroll
        for (int i = 0; i < 16; ++i) {
            const int p = lane + 32 * i;       // 512 x 16B pieces (32 rows x 64 f)
            const int r = p >> 4;
            const int cf = (p & 15) << 2;
            cp_async16(wbuf + r * NODE_STRIDE + cf, gnode + r * 64 + cf);
        }
        cp_commit();
        cp_wait<0>();
        __syncwarp();
#pragma unroll
        for (int j = 0; j < 2; ++j)
#pragma unroll
            for (int s = 0; s < 8; ++s) {
                const int r0 = 16 * j + qr;
                naf[j][s][0] = f2tf(wbuf[r0 * NODE_STRIDE + 8 * s + qc]);
                naf[j][s][1] = f2tf(wbuf[(r0 + 8) * NODE_STRIDE + 8 * s + qc]);
                naf[j][s][2] = f2tf(wbuf[r0 * NODE_STRIDE + 8 * s + qc + 4]);
                naf[j][s][3] = f2tf(wbuf[(r0 + 8) * NODE_STRIDE + 8 * s + qc + 4]);
            }
        __syncwarp();   // frag extraction done before adj loads overwrite slots
    }

    const float* adj_b = adj + (((size_t)b * E_SZ) << 16);

    // ---- kick off edge-0 adj chunks 0..2 immediately ----
    {
        const float* adj_w0 = adj_b + mrow * 256;
        issue_adj_warp(wbuf,                   adj_w0, 0, lane); cp_commit();
        issue_adj_warp(wbuf + 1 * WBUF_FLOATS, adj_w0, 1, lane); cp_commit();
        issue_adj_warp(wbuf + 2 * WBUF_FLOATS, adj_w0, 2, lane); cp_commit();
    }

    // ---- residual: out_acc = node @ W_add + b_add (overlaps edge-0 adj loads) ----
    load_W_bias(sh_w, sh_bias, W_add, b_add, tid);
    __syncthreads();   // W_add + bias visible

    float oacc[2][8][4];
    init_bias(sh_bias, qc, oacc);
    gemm_nodeW(naf, sh_w, qr, qc, oacc);

    // ---- edge-type loop ----
    for (int e = 0; e < E_SZ; ++e) {
        const float* adj_w  = adj_b + ((size_t)e << 16) + mrow * 256;
        const float* adj_wn = adj_b + ((size_t)(e + 1) << 16) + mrow * 256; // next edge

        __syncthreads();   // all warps done with prev sh_w + prev sh_hid reads
        load_W_bias(sh_w, sh_bias, W_edge + e * 4096, b_edge + e * 64, tid);
        __syncthreads();   // W_e + bias visible

        // stage 1: hidden_e = node @ W_e + b_e  -> sh_hid (tf32, pair-interleaved)
        {
            float hacc[2][8][4];
            init_bias(sh_bias, qc, hacc);
            gemm_nodeW(naf, sh_w, qr, qc, hacc);
#pragma unroll
            for (int j = 0; j < 2; ++j) {
                const int a0 = ((mrow >> 3) << 9) + (j << 10)
                             + ((qr & 3) << 1) + (qr >> 2);
#pragma unroll
                for (int nt = 0; nt < 8; ++nt) {
                    const int an = a0 + ((8 * nt + 2 * qc) << 3);
                    sh_hid[an]       = __uint_as_float(f2tf(hacc[j][nt][0])); // (k,   n)
                    sh_hid[an + 8]   = __uint_as_float(f2tf(hacc[j][nt][1])); // (k,   n+1)
                    sh_hid[an + 512] = __uint_as_float(f2tf(hacc[j][nt][2])); // (k+8, n)
                    sh_hid[an + 520] = __uint_as_float(f2tf(hacc[j][nt][3])); // (k+8, n+1)
                }
            }
        }
        __syncthreads();   // hidden visible to all warps

        // stage 2: out_acc += adj_e @ hidden_e — per-warp 4-stage pipeline with
        // seamless cross-edge refill (slots freed at kc>=5 take next edge's 0..2)
#pragma unroll
        for (int kc = 0; kc < 8; ++kc) {
            __syncwarp();   // all lanes done with the chunk whose slot refills now
            if (kc < 5) {
                issue_adj_warp(wbuf + ((kc + 3) & 3) * WBUF_FLOATS, adj_w, kc + 3, lane);
                cp_commit();
                cp_wait<3>();
            } else if (e < E_SZ - 1) {
                issue_adj_warp(wbuf + ((kc + 3) & 3) * WBUF_FLOATS, adj_wn, kc - 5, lane);
                cp_commit();
                cp_wait<3>();
            } else {
                if (kc == 5)      cp_wait<2>();
                else if (kc == 6) cp_wait<1>();
                else              cp_wait<0>();
            }
            __syncwarp();   // chunk kc visible to all lanes of this warp

            const float* abuf = wbuf + (kc & 3) * WBUF_FLOATS;
#pragma unroll
            for (int s = 0; s < 4; ++s) {
                const float* gbase = sh_hid + ((4 * kc + s) << 9);
                uint32_t bf[8][2];
#pragma unroll
                for (int nt = 0; nt < 8; ++nt) {
                    // {hid[k0+qc][n], hid[k0+qc+4][n]} as one LDS.64
                    uint2 p = *(const uint2*)&gbase[((8 * nt + qr) << 3) + (qc << 1)];
                    bf[nt][0] = p.x; bf[nt][1] = p.y;
                }
                const int cl = 8 * s + qc;
#pragma unroll
                for (int j = 0; j < 2; ++j) {
                    const int lr = 16 * j + qr;          // local row in warp slot
                    uint32_t af[4];
                    af[0] = *(const uint32_t*)&abuf[lr * ADJ_STRIDE + cl];
                    af[1] = *(const uint32_t*)&abuf[(lr + 8) * ADJ_STRIDE + cl];
                    af[2] = *(const uint32_t*)&abuf[lr * ADJ_STRIDE + cl + 4];
                    af[3] = *(const uint32_t*)&abuf[(lr + 8) * ADJ_STRIDE + cl + 4];
#pragma unroll
                    for (int nt = 0; nt < 8; ++nt) mma_tf32(oacc[j][nt], af, bf[nt]);
                }
            }
        }
        __syncwarp();   // last chunk's reads done before anything refills slots
    }

    // ---- epilogue: write out[b] ----
    float* ob = out + (size_t)b * N_SZ * F_SZ;
#pragma unroll
    for (int j = 0; j < 2; ++j) {
#pragma unroll
        for (int nt = 0; nt < 8; ++nt) {
            const int r0 = mrow + 16 * j + qr;
            const int c0 = 8 * nt + 2 * qc;
            *(float2*)&ob[r0 * 64 + c0]       = make_float2(oacc[j][nt][0], oacc[j][nt][1]);
            *(float2*)&ob[(r0 + 8) * 64 + c0] = make_float2(oacc[j][nt][2], oacc[j][nt][3]);
        }
    }
}

extern "C" void kernel_launch(void* const* d_in, const int* in_sizes, int n_in,
                              void* d_out, int out_size) {
    const float* node   = (const float*)d_in[0];
    const float* adj    = (const float*)d_in[1];
    const float* W_edge = (const float*)d_in[2];
    const float* b_edge = (const float*)d_in[3];
    const float* W_add  = (const float*)d_in[4];
    const float* b_add  = (const float*)d_in[5];
    float* out = (float*)d_out;

    cudaFuncSetAttribute(graphconv_tf32_kernel,
                         cudaFuncAttributeMaxDynamicSharedMemorySize, SMEM_BYTES);
    graphconv_tf32_kernel<<<512, NTHREADS, SMEM_BYTES>>>(node, adj, W_edge, b_edge,
                                                         W_add, b_add, out);
}